// round 1
// baseline (speedup 1.0000x reference)
#include <cuda_runtime.h>
#include <cuda_bf16.h>
#include <math_constants.h>

// Problem constants
#define NB   16
#define NC   1024
#define NT   16
#define NP   360          // H*W = 12*30
#define NK   120          // top-k
#define ROWS 482          // 1 + 120 + 1 + 360
#define CSPLIT 8
#define CCHUNK (NC / CSPLIT)   // 128
#define TSTRIDE ((size_t)NT * NP)   // 5760 floats between consecutive c

// Scratch (no device allocation allowed -> __device__ globals)
__device__ float g_spart[NB][CSPLIT][384];
__device__ int   g_posmap[NB][NP];

// ---------------------------------------------------------------------------
// K1: partial dot products  scores_part[b][cs][p] = sum_{c in chunk} cls[b,0,c]*x[b,c,0,p]
// grid (NB, CSPLIT), block 384.  Lanes are consecutive p -> fully coalesced x reads.
// ---------------------------------------------------------------------------
__global__ void k_scores(const float* __restrict__ x, const float* __restrict__ cls)
{
    const int b  = blockIdx.x;
    const int cs = blockIdx.y;
    const int p  = threadIdx.x;

    __shared__ float cls_s[CCHUNK];
    if (threadIdx.x < CCHUNK)
        cls_s[threadIdx.x] = cls[b * (NT * NC) + cs * CCHUNK + threadIdx.x]; // t=0
    __syncthreads();

    if (p >= NP) return;

    const float* xb = x + ((size_t)b * NC + cs * CCHUNK) * TSTRIDE + p; // t=0 offset = 0
    float s0 = 0.f, s1 = 0.f;
    #pragma unroll 8
    for (int i = 0; i < CCHUNK; i += 2) {
        s0 = fmaf(cls_s[i],     xb[(size_t)i * TSTRIDE],       s0);
        s1 = fmaf(cls_s[i + 1], xb[(size_t)(i + 1) * TSTRIDE], s1);
    }
    g_spart[b][cs][p] = s0 + s1;
}

// ---------------------------------------------------------------------------
// K2: per-b reduce partials (fixed order -> deterministic), bitonic sort 512
// (score desc, idx asc tiebreak = lax.top_k semantics), build posmap, copy cls rows.
// grid NB, block 512.
// ---------------------------------------------------------------------------
__global__ void k_sort(const float* __restrict__ cls, float* __restrict__ out)
{
    const int b   = blockIdx.x;
    const int tid = threadIdx.x;

    __shared__ float sv[512];
    __shared__ int   si[512];

    float v = -CUDART_INF_F;
    if (tid < NP) {
        float a = 0.f;
        #pragma unroll
        for (int cs = 0; cs < CSPLIT; ++cs) a += g_spart[b][cs][tid];
        v = a;
    }
    sv[tid] = v;
    si[tid] = tid;
    __syncthreads();

    // bitonic sort, descending by (score, then ascending idx)
    for (int k = 2; k <= 512; k <<= 1) {
        for (int j = k >> 1; j > 0; j >>= 1) {
            const int ixj = tid ^ j;
            if (ixj > tid) {
                const float a = sv[tid], c = sv[ixj];
                const int   ia = si[tid], ic = si[ixj];
                const bool a_after = (a < c) || (a == c && ia > ic); // a belongs after c (desc)
                const bool dir_desc = ((tid & k) == 0);
                const bool sw = dir_desc ? a_after : !a_after;
                if (sw) { sv[tid] = c; sv[ixj] = a; si[tid] = ic; si[ixj] = ia; }
            }
            __syncthreads();
        }
    }

    // inverse map: selected p -> output row (1..120), else -1
    if (tid < NP) g_posmap[b][tid] = -1;
    __syncthreads();
    if (tid < NK) g_posmap[b][si[tid]] = 1 + tid;

    // cls rows: row 0 = cls[b,0,:], row 121 = cls[b,1,:]
    const size_t obase = (size_t)b * ROWS * NC;
    for (int c = tid; c < NC; c += 512) {
        out[obase + c]              = cls[b * (NT * NC) + c];
        out[obase + 121 * NC + c]   = cls[b * (NT * NC) + NC + c];
    }
}

// ---------------------------------------------------------------------------
// K3: tiled transpose copy.
//   t=0: rows posmap[p] (selected 120 of 360), t=1: rows 122+p (all 360).
// grid (32 c-tiles, 12 p-tiles, NB*2), block (32,8).
// Loads coalesced over p (contiguous), stores coalesced over c.
// ---------------------------------------------------------------------------
__global__ void k_copy(const float* __restrict__ x, float* __restrict__ out)
{
    const int ct = blockIdx.x;          // 0..31
    const int pt = blockIdx.y;          // 0..11
    const int b  = blockIdx.z >> 1;
    const int t  = blockIdx.z & 1;

    __shared__ float tile[32][33];

    const int p = pt * 32 + threadIdx.x;
    const float* xb = x + ((size_t)b * NC + ct * 32) * TSTRIDE + (size_t)t * NP;

    if (p < NP) {
        #pragma unroll
        for (int r = 0; r < 4; ++r) {
            const int cl = threadIdx.y + r * 8;
            tile[cl][threadIdx.x] = xb[(size_t)cl * TSTRIDE + p];
        }
    }
    __syncthreads();

    const int c_out = ct * 32 + threadIdx.x;
    const size_t obase = (size_t)b * ROWS * NC;
    #pragma unroll
    for (int r = 0; r < 4; ++r) {
        const int pl = threadIdx.y + r * 8;
        const int pg = pt * 32 + pl;
        if (pg < NP) {
            const int row = t ? (122 + pg) : g_posmap[b][pg];
            if (row >= 0)
                out[obase + (size_t)row * NC + c_out] = tile[threadIdx.x][pl];
        }
    }
}

// ---------------------------------------------------------------------------
extern "C" void kernel_launch(void* const* d_in, const int* in_sizes, int n_in,
                              void* d_out, int out_size)
{
    const float* x   = (const float*)d_in[0];   // [16,1024,16,12,30]
    const float* cls = (const float*)d_in[1];   // [16,16,1024]
    float* out = (float*)d_out;                 // [16,482,1024]

    k_scores<<<dim3(NB, CSPLIT), 384>>>(x, cls);
    k_sort<<<NB, 512>>>(cls, out);
    k_copy<<<dim3(32, 12, NB * 2), dim3(32, 8)>>>(x, out);
}

// round 2
// speedup vs baseline: 1.1848x; 1.1848x over previous
#include <cuda_runtime.h>
#include <cuda_bf16.h>
#include <math_constants.h>

// Problem constants
#define NB   16
#define NC   1024
#define NT   16
#define NP   360          // H*W = 12*30
#define NK   120          // top-k
#define ROWS 482          // 1 + 120 + 1 + 360
#define CSPLIT 32
#define CCHUNK (NC / CSPLIT)        // 32
#define TSTRIDE ((size_t)NT * NP)   // 5760 floats between consecutive c
#define CTILE 128                   // K3: c per tile

// Scratch (no device allocation allowed -> __device__ globals)
__device__ __align__(16) float g_spart[NB][CSPLIT][NP];
__device__ int g_posmap[NB][NP];

// ---------------------------------------------------------------------------
// K1: partial dots. scores_part[b][cs][p] = sum_{c in chunk} cls[b,0,c]*x[b,c,0,p]
// grid (NB, CSPLIT) = 512 blocks, block 96 (90 active). Each thread owns a
// float4 p-quad -> 512B/warp per load, high MLP (full unroll over 32 c).
// ---------------------------------------------------------------------------
__global__ void k_scores(const float* __restrict__ x, const float* __restrict__ cls)
{
    const int b  = blockIdx.x;
    const int cs = blockIdx.y;
    const int tid = threadIdx.x;

    __shared__ float cls_s[CCHUNK];
    if (tid < CCHUNK)
        cls_s[tid] = cls[b * (NT * NC) + cs * CCHUNK + tid];   // t=0
    __syncthreads();

    if (tid >= NP / 4) return;   // 90 active threads

    const float4* xp = reinterpret_cast<const float4*>(
        x + ((size_t)b * NC + (size_t)cs * CCHUNK) * TSTRIDE) + tid;

    float4 acc = make_float4(0.f, 0.f, 0.f, 0.f);
    #pragma unroll
    for (int i = 0; i < CCHUNK; ++i) {
        const float4 v = xp[(size_t)i * (TSTRIDE / 4)];
        const float  w = cls_s[i];
        acc.x = fmaf(w, v.x, acc.x);
        acc.y = fmaf(w, v.y, acc.y);
        acc.z = fmaf(w, v.z, acc.z);
        acc.w = fmaf(w, v.w, acc.w);
    }
    *reinterpret_cast<float4*>(&g_spart[b][cs][tid * 4]) = acc;
}

// ---------------------------------------------------------------------------
// K2: per-b reduce partials (fixed order -> deterministic), bitonic sort 512
// (score desc, idx asc tiebreak = lax.top_k semantics), build posmap, copy
// the two cls rows. grid NB, block 512.
// ---------------------------------------------------------------------------
__global__ void k_sort(const float* __restrict__ cls, float* __restrict__ out)
{
    const int b   = blockIdx.x;
    const int tid = threadIdx.x;

    __shared__ float sv[512];
    __shared__ int   si[512];

    float v = -CUDART_INF_F;
    if (tid < NP) {
        float a = 0.f;
        #pragma unroll
        for (int cs = 0; cs < CSPLIT; ++cs) a += g_spart[b][cs][tid];
        v = a;
    }
    sv[tid] = v;
    si[tid] = tid;
    __syncthreads();

    // bitonic sort, descending by (score, then ascending idx)
    for (int k = 2; k <= 512; k <<= 1) {
        for (int j = k >> 1; j > 0; j >>= 1) {
            const int ixj = tid ^ j;
            if (ixj > tid) {
                const float a = sv[tid], c = sv[ixj];
                const int   ia = si[tid], ic = si[ixj];
                const bool a_after = (a < c) || (a == c && ia > ic);
                const bool dir_desc = ((tid & k) == 0);
                const bool sw = dir_desc ? a_after : !a_after;
                if (sw) { sv[tid] = c; sv[ixj] = a; si[tid] = ic; si[ixj] = ia; }
            }
            __syncthreads();
        }
    }

    if (tid < NP) g_posmap[b][tid] = -1;
    __syncthreads();
    if (tid < NK) g_posmap[b][si[tid]] = 1 + tid;

    // cls rows: row 0 = cls[b,0,:], row 121 = cls[b,1,:]
    const size_t obase = (size_t)b * ROWS * NC;
    const float4* c4 = reinterpret_cast<const float4*>(cls + (size_t)b * NT * NC);
    float4* o4 = reinterpret_cast<float4*>(out + obase);
    for (int c = tid; c < NC / 4; c += 512) {
        o4[c]                 = c4[c];                // row 0
        o4[121 * (NC/4) + c]  = c4[(NC/4) + c];       // row 121 (t=1 cls)
    }
}

// ---------------------------------------------------------------------------
// K3: tiled transpose copy, 128c x 32p per block, float4 both sides.
//   t=0: rows posmap[p] (selected 120 of 360), t=1: rows 122+p (all 360).
// grid (8 c-tiles, 12 p-tiles, NB*2), block 256.
// smem tile stored [p][c] so the store side is LDS.128 conflict-free.
// ---------------------------------------------------------------------------
__global__ void k_copy(const float* __restrict__ x, float* __restrict__ out)
{
    const int ct = blockIdx.x;          // 0..7   (c tile of 128)
    const int pt = blockIdx.y;          // 0..11  (p tile of 32)
    const int b  = blockIdx.z >> 1;
    const int t  = blockIdx.z & 1;
    const int tid = threadIdx.x;

    __shared__ __align__(16) float tile[32][132];   // [p_local][c_local], padded

    // ---- load: 1024 float4 loads (128 c rows x 8 p-quads), 4 per thread ----
    const float* xbase = x + (size_t)(b * NC + ct * CTILE) * TSTRIDE + (size_t)t * NP;
    #pragma unroll
    for (int i = 0; i < 4; ++i) {
        const int s  = tid + 256 * i;
        const int pq = s & 7;           // p-quad within tile
        const int cl = s >> 3;          // c local 0..127
        const int pbase = pt * 32 + pq * 4;
        if (pbase < NP) {
            const float4 v = *reinterpret_cast<const float4*>(
                xbase + (size_t)cl * TSTRIDE + pbase);
            const int pl = pq * 4;
            tile[pl + 0][cl] = v.x;
            tile[pl + 1][cl] = v.y;
            tile[pl + 2][cl] = v.z;
            tile[pl + 3][cl] = v.w;
        }
    }
    __syncthreads();

    // ---- store: 1024 float4 stores (32 p rows x 32 c-quads), 4 per thread ----
    const size_t obase = (size_t)b * ROWS * NC;
    #pragma unroll
    for (int i = 0; i < 4; ++i) {
        const int s  = tid + 256 * i;
        const int cq = s & 31;          // c-quad 0..31
        const int pl = s >> 5;          // p local 0..31
        const int pg = pt * 32 + pl;
        if (pg < NP) {
            const int row = t ? (122 + pg) : g_posmap[b][pg];
            if (row >= 0) {
                const float4 w = *reinterpret_cast<const float4*>(&tile[pl][cq * 4]);
                *reinterpret_cast<float4*>(
                    out + obase + (size_t)row * NC + ct * CTILE + cq * 4) = w;
            }
        }
    }
}

// ---------------------------------------------------------------------------
extern "C" void kernel_launch(void* const* d_in, const int* in_sizes, int n_in,
                              void* d_out, int out_size)
{
    const float* x   = (const float*)d_in[0];   // [16,1024,16,12,30]
    const float* cls = (const float*)d_in[1];   // [16,16,1024]
    float* out = (float*)d_out;                 // [16,482,1024]

    k_scores<<<dim3(NB, CSPLIT), 96>>>(x, cls);
    k_sort<<<NB, 512>>>(cls, out);
    k_copy<<<dim3(8, 12, NB * 2), 256>>>(x, out);
}

// round 3
// speedup vs baseline: 1.3007x; 1.0979x over previous
#include <cuda_runtime.h>
#include <cuda_bf16.h>
#include <math_constants.h>

// Problem constants
#define NB   16
#define NC   1024
#define NT   16
#define NP   360          // H*W = 12*30
#define NK   120          // top-k
#define ROWS 482          // 1 + 120 + 1 + 360
#define CSPLIT 32
#define CCHUNK (NC / CSPLIT)        // 32
#define TSTRIDE ((size_t)NT * NP)   // 5760 floats between consecutive c

// Scratch (no device allocation allowed -> __device__ globals)
__device__ __align__(16) float g_spart[NB][CSPLIT][NP];
__device__ int g_posmap[NB][NP];

// ---------------------------------------------------------------------------
// K1: partial dots. scores_part[b][cs][p] = sum_{c in chunk} cls[b,0,c]*x[b,c,0,p]
// grid (16, 32) = 512 blocks, block 96 (90 active p-quads).
// Explicit register batches of 8 float4 loads -> real MLP=8 per thread.
// ---------------------------------------------------------------------------
__global__ void __launch_bounds__(96) k_scores(const float* __restrict__ x,
                                               const float* __restrict__ cls)
{
    const int b   = blockIdx.x;
    const int cs  = blockIdx.y;
    const int tid = threadIdx.x;

    __shared__ float cls_s[CCHUNK];
    if (tid < CCHUNK)
        cls_s[tid] = cls[b * (NT * NC) + cs * CCHUNK + tid];   // t=0
    __syncthreads();

    if (tid >= NP / 4) return;   // 90 active threads

    const float4* xp = reinterpret_cast<const float4*>(
        x + ((size_t)b * NC + (size_t)cs * CCHUNK) * TSTRIDE) + tid;

    float4 acc = make_float4(0.f, 0.f, 0.f, 0.f);
    float4 v[8];

    #pragma unroll
    for (int batch = 0; batch < CCHUNK / 8; ++batch) {
        const int base = batch * 8;
        #pragma unroll
        for (int j = 0; j < 8; ++j)
            v[j] = xp[(size_t)(base + j) * (TSTRIDE / 4)];
        #pragma unroll
        for (int j = 0; j < 8; ++j) {
            const float w = cls_s[base + j];
            acc.x = fmaf(w, v[j].x, acc.x);
            acc.y = fmaf(w, v[j].y, acc.y);
            acc.z = fmaf(w, v[j].z, acc.z);
            acc.w = fmaf(w, v[j].w, acc.w);
        }
    }
    *reinterpret_cast<float4*>(&g_spart[b][cs][tid * 4]) = acc;
}

// ---------------------------------------------------------------------------
// K2: per-b reduce partials (fixed order -> deterministic), bitonic sort 512
// (score desc, idx asc tiebreak = lax.top_k semantics), build posmap, copy
// the two cls rows. grid 16, block 512.
// ---------------------------------------------------------------------------
__global__ void k_sort(const float* __restrict__ cls, float* __restrict__ out)
{
    const int b   = blockIdx.x;
    const int tid = threadIdx.x;

    __shared__ float sv[512];
    __shared__ int   si[512];

    float v = -CUDART_INF_F;
    if (tid < NP) {
        float a0 = 0.f, a1 = 0.f;
        #pragma unroll
        for (int cs = 0; cs < CSPLIT; cs += 2) {
            a0 += g_spart[b][cs][tid];
            a1 += g_spart[b][cs + 1][tid];
        }
        v = a0 + a1;
    }
    sv[tid] = v;
    si[tid] = tid;
    __syncthreads();

    // bitonic sort, descending by (score, then ascending idx)
    for (int k = 2; k <= 512; k <<= 1) {
        for (int j = k >> 1; j > 0; j >>= 1) {
            const int ixj = tid ^ j;
            if (ixj > tid) {
                const float a = sv[tid], c = sv[ixj];
                const int   ia = si[tid], ic = si[ixj];
                const bool a_after = (a < c) || (a == c && ia > ic);
                const bool dir_desc = ((tid & k) == 0);
                const bool sw = dir_desc ? a_after : !a_after;
                if (sw) { sv[tid] = c; sv[ixj] = a; si[tid] = ic; si[ixj] = ia; }
            }
            __syncthreads();
        }
    }

    if (tid < NP) g_posmap[b][tid] = -1;
    __syncthreads();
    if (tid < NK) g_posmap[b][si[tid]] = 1 + tid;

    // cls rows: row 0 = cls[b,0,:], row 121 = cls[b,1,:]
    const size_t obase = (size_t)b * ROWS * NC;
    const float4* c4 = reinterpret_cast<const float4*>(cls + (size_t)b * NT * NC);
    float4* o4 = reinterpret_cast<float4*>(out + obase);
    for (int c = tid; c < NC / 4; c += 512) {
        o4[c]                 = c4[c];               // row 0   (t=0 cls)
        o4[121 * (NC/4) + c]  = c4[(NC/4) + c];      // row 121 (t=1 cls)
    }
}

// ---------------------------------------------------------------------------
// K3: tiled transpose copy, 32c x 128p per block, float4 on both gmem sides.
// smem is component-split: tiles[j][c*33 + pq] holds x[c][4*pq + j].
//   STS banks = (j + c + pq) % 32        -> conflict-free (pq varies in warp)
//   LDS banks = (j + 4cq + k + pq) % 32  -> conflict-free (j,cq vary in warp)
//   t=0: rows posmap[p] (selected 120 of 360), t=1: rows 122+p (all 360).
// grid (32 c-tiles, 3 p-tiles, NB*2), block 256.
// ---------------------------------------------------------------------------
__global__ void k_copy(const float* __restrict__ x, float* __restrict__ out)
{
    const int ct = blockIdx.x;          // 0..31  (c tile of 32)
    const int pt = blockIdx.y;          // 0..2   (p tile of 128)
    const int b  = blockIdx.z >> 1;
    const int t  = blockIdx.z & 1;
    const int tid = threadIdx.x;

    __shared__ float tiles[4][1057];    // stride 1057 == 1 (mod 32)

    const float* xbase = x + (size_t)(b * NC + ct * 32) * TSTRIDE + (size_t)t * NP;
    const int pbase = pt * 128;

    // ---- load: 32 c-rows x 32 p-quads, 4 float4 loads per thread ----
    #pragma unroll
    for (int i = 0; i < 4; ++i) {
        const int s  = tid + 256 * i;
        const int cl = s >> 5;          // 0..31 (fixed within a warp)
        const int pq = s & 31;          // 0..31
        const int p  = pbase + pq * 4;
        if (p < NP) {
            const float4 v = *reinterpret_cast<const float4*>(
                xbase + (size_t)cl * TSTRIDE + p);
            const int idx = cl * 33 + pq;
            tiles[0][idx] = v.x;
            tiles[1][idx] = v.y;
            tiles[2][idx] = v.z;
            tiles[3][idx] = v.w;
        }
    }
    __syncthreads();

    // ---- store: 128 p-rows x 8 c-quads, 4 float4 stores per thread ----
    const size_t obase = (size_t)b * ROWS * NC;
    #pragma unroll
    for (int i = 0; i < 4; ++i) {
        const int s  = tid + 256 * i;
        const int cq = s & 7;           // 0..7
        const int pl = s >> 3;          // 0..127
        const int pg = pbase + pl;
        if (pg < NP) {
            const int row = t ? (122 + pg) : g_posmap[b][pg];
            if (row >= 0) {
                const int j  = pl & 3;
                const int pq = pl >> 2;
                float4 w;
                w.x = tiles[j][(4 * cq + 0) * 33 + pq];
                w.y = tiles[j][(4 * cq + 1) * 33 + pq];
                w.z = tiles[j][(4 * cq + 2) * 33 + pq];
                w.w = tiles[j][(4 * cq + 3) * 33 + pq];
                *reinterpret_cast<float4*>(
                    out + obase + (size_t)row * NC + ct * 32 + cq * 4) = w;
            }
        }
    }
}

// ---------------------------------------------------------------------------
extern "C" void kernel_launch(void* const* d_in, const int* in_sizes, int n_in,
                              void* d_out, int out_size)
{
    const float* x   = (const float*)d_in[0];   // [16,1024,16,12,30]
    const float* cls = (const float*)d_in[1];   // [16,16,1024]
    float* out = (float*)d_out;                 // [16,482,1024]

    k_scores<<<dim3(NB, CSPLIT), 96>>>(x, cls);
    k_sort<<<NB, 512>>>(cls, out);
    k_copy<<<dim3(32, 3, NB * 2), 256>>>(x, out);
}

// round 5
// speedup vs baseline: 1.6667x; 1.2813x over previous
#include <cuda_runtime.h>
#include <cuda_bf16.h>
#include <math_constants.h>

// Problem constants
#define NB   16
#define NC   1024
#define NT   16
#define NP   360          // H*W = 12*30
#define NK   120          // top-k
#define ROWS 482          // 1 + 120 + 1 + 360
#define CSPLIT 32
#define CCHUNK (NC / CSPLIT)        // 32
#define TSTRIDE ((size_t)NT * NP)   // 5760 floats between consecutive c

// Scratch (no device allocation allowed -> __device__ globals)
__device__ __align__(16) float g_spart[NB][CSPLIT][NP];
__device__ int g_posmap[NB][NP];

// ---------------------------------------------------------------------------
// K1: partial dots. scores_part[b][cs][p] = sum_{c in chunk} cls[b,0,c]*x[b,c,0,p]
// grid (16, 32) = 512 blocks, 96 threads (90 active p-quads).
// __launch_bounds__(96, 2) lifts the 32-reg occupancy clamp so the v[16]
// batch really holds 16 float4 loads in flight per thread (MLP=16).
// ---------------------------------------------------------------------------
__global__ void __launch_bounds__(96, 2) k_scores(const float* __restrict__ x,
                                                  const float* __restrict__ cls)
{
    const int b   = blockIdx.x;
    const int cs  = blockIdx.y;
    const int tid = threadIdx.x;

    __shared__ float cls_s[CCHUNK];
    if (tid < CCHUNK)
        cls_s[tid] = cls[b * (NT * NC) + cs * CCHUNK + tid];   // t=0
    __syncthreads();

    if (tid >= NP / 4) return;   // 90 active threads

    const float4* xp = reinterpret_cast<const float4*>(
        x + ((size_t)b * NC + (size_t)cs * CCHUNK) * TSTRIDE) + tid;

    float4 acc = make_float4(0.f, 0.f, 0.f, 0.f);
    float4 v[16];

    #pragma unroll
    for (int batch = 0; batch < CCHUNK / 16; ++batch) {
        const int base = batch * 16;
        #pragma unroll
        for (int j = 0; j < 16; ++j)
            v[j] = xp[(size_t)(base + j) * (TSTRIDE / 4)];
        #pragma unroll
        for (int j = 0; j < 16; ++j) {
            const float w = cls_s[base + j];
            acc.x = fmaf(w, v[j].x, acc.x);
            acc.y = fmaf(w, v[j].y, acc.y);
            acc.z = fmaf(w, v[j].z, acc.z);
            acc.w = fmaf(w, v[j].w, acc.w);
        }
    }
    *reinterpret_cast<float4*>(&g_spart[b][cs][tid * 4]) = acc;
}

// ---------------------------------------------------------------------------
// K2 (fused): heterogeneous grid, 256 threads.
//   blocks 0..15        : per-b reduce + bitonic sort 512 (desc score, asc idx
//                         tiebreak = lax.top_k), build posmap, copy cls rows.
//   blocks 16..16+1535  : frame-1 transpose copy (independent of sort),
//                         32c x 128p tiles, float4 both gmem sides,
//                         conflict-free component-split smem.
// The ~3us sort hides under the ~6us frame-1 stream.
// ---------------------------------------------------------------------------
__global__ void __launch_bounds__(256) k_mid(const float* __restrict__ x,
                                             const float* __restrict__ cls,
                                             float* __restrict__ out)
{
    __shared__ float sv[512];
    __shared__ int   si[512];
    __shared__ float tiles[4][1057];    // stride 1057 == 1 (mod 32)

    const int tid = threadIdx.x;

    if (blockIdx.x < NB) {
        // ---------------- sort path ----------------
        const int b = blockIdx.x;

        for (int e = tid; e < 512; e += 256) {
            float vsum = -CUDART_INF_F;
            if (e < NP) {
                float a0 = 0.f, a1 = 0.f;
                #pragma unroll
                for (int cs = 0; cs < CSPLIT; cs += 2) {
                    a0 += g_spart[b][cs][e];
                    a1 += g_spart[b][cs + 1][e];
                }
                vsum = a0 + a1;
            }
            sv[e] = vsum;
            si[e] = e;
        }
        __syncthreads();

        // bitonic: 256 threads, one compare-exchange pair each substage
        for (int k = 2; k <= 512; k <<= 1) {
            for (int j = k >> 1; j > 0; j >>= 1) {
                const int l = 2 * tid - (tid & (j - 1));   // l & j == 0
                const int m = l | j;
                const float a = sv[l], c = sv[m];
                const int   ia = si[l], ic = si[m];
                const bool a_after = (a < c) || (a == c && ia > ic); // after c in desc order
                const bool dir_desc = ((l & k) == 0);
                if (dir_desc ? a_after : !a_after) {
                    sv[l] = c; sv[m] = a; si[l] = ic; si[m] = ia;
                }
                __syncthreads();
            }
        }

        for (int p = tid; p < NP; p += 256) g_posmap[b][p] = -1;
        __syncthreads();
        if (tid < NK) g_posmap[b][si[tid]] = 1 + tid;

        // cls rows: row 0 = cls[b,0,:], row 121 = cls[b,1,:]
        const size_t obase = (size_t)b * ROWS * NC;
        const float4* c4 = reinterpret_cast<const float4*>(cls + (size_t)b * NT * NC);
        float4* o4 = reinterpret_cast<float4*>(out + obase);
        for (int c = tid; c < NC / 4; c += 256) {
            o4[c]                = c4[c];               // row 0   (t=0 cls)
            o4[121 * (NC/4) + c] = c4[(NC/4) + c];      // row 121 (t=1 cls)
        }
    } else {
        // ---------------- frame-1 copy path ----------------
        const int bid = blockIdx.x - NB;     // 0..1535
        const int ct  = bid & 31;            // c tile of 32
        const int rem = bid >> 5;
        const int pt  = rem % 3;             // p tile of 128
        const int b   = rem / 3;             // 0..15

        const float* xbase = x + (size_t)(b * NC + ct * 32) * TSTRIDE + NP; // t=1
        const int pbase = pt * 128;

        #pragma unroll
        for (int i = 0; i < 4; ++i) {
            const int s  = tid + 256 * i;
            const int cl = s >> 5;           // 0..31
            const int pq = s & 31;           // 0..31
            const int p  = pbase + pq * 4;
            if (p < NP) {
                const float4 v = *reinterpret_cast<const float4*>(
                    xbase + (size_t)cl * TSTRIDE + p);
                const int idx = cl * 33 + pq;
                tiles[0][idx] = v.x;
                tiles[1][idx] = v.y;
                tiles[2][idx] = v.z;
                tiles[3][idx] = v.w;
            }
        }
        __syncthreads();

        const size_t obase = (size_t)b * ROWS * NC;
        #pragma unroll
        for (int i = 0; i < 4; ++i) {
            const int s  = tid + 256 * i;
            const int cq = s & 7;            // 0..7
            const int pl = s >> 3;           // 0..127
            const int pg = pbase + pl;
            if (pg < NP) {
                const int row = 122 + pg;
                const int j  = pl & 3;
                const int pq = pl >> 2;
                float4 w;
                w.x = tiles[j][(4 * cq + 0) * 33 + pq];
                w.y = tiles[j][(4 * cq + 1) * 33 + pq];
                w.z = tiles[j][(4 * cq + 2) * 33 + pq];
                w.w = tiles[j][(4 * cq + 3) * 33 + pq];
                *reinterpret_cast<float4*>(
                    out + obase + (size_t)row * NC + ct * 32 + cq * 4) = w;
            }
        }
    }
}

// ---------------------------------------------------------------------------
// K3: frame-0 selective transpose copy (reads are L2-warm from K1/K2).
// grid (32, 3, 16), block 256. Only rows with posmap >= 0 are stored.
// ---------------------------------------------------------------------------
__global__ void __launch_bounds__(256) k_copy0(const float* __restrict__ x,
                                               float* __restrict__ out)
{
    const int ct = blockIdx.x;          // 0..31
    const int pt = blockIdx.y;          // 0..2
    const int b  = blockIdx.z;
    const int tid = threadIdx.x;

    __shared__ float tiles[4][1057];

    const float* xbase = x + (size_t)(b * NC + ct * 32) * TSTRIDE;  // t=0
    const int pbase = pt * 128;

    #pragma unroll
    for (int i = 0; i < 4; ++i) {
        const int s  = tid + 256 * i;
        const int cl = s >> 5;
        const int pq = s & 31;
        const int p  = pbase + pq * 4;
        if (p < NP) {
            const float4 v = *reinterpret_cast<const float4*>(
                xbase + (size_t)cl * TSTRIDE + p);
            const int idx = cl * 33 + pq;
            tiles[0][idx] = v.x;
            tiles[1][idx] = v.y;
            tiles[2][idx] = v.z;
            tiles[3][idx] = v.w;
        }
    }
    __syncthreads();

    const size_t obase = (size_t)b * ROWS * NC;
    #pragma unroll
    for (int i = 0; i < 4; ++i) {
        const int s  = tid + 256 * i;
        const int cq = s & 7;
        const int pl = s >> 3;
        const int pg = pbase + pl;
        if (pg < NP) {
            const int row = g_posmap[b][pg];
            if (row >= 0) {
                const int j  = pl & 3;
                const int pq = pl >> 2;
                float4 w;
                w.x = tiles[j][(4 * cq + 0) * 33 + pq];
                w.y = tiles[j][(4 * cq + 1) * 33 + pq];
                w.z = tiles[j][(4 * cq + 2) * 33 + pq];
                w.w = tiles[j][(4 * cq + 3) * 33 + pq];
                *reinterpret_cast<float4*>(
                    out + obase + (size_t)row * NC + ct * 32 + cq * 4) = w;
            }
        }
    }
}

// ---------------------------------------------------------------------------
extern "C" void kernel_launch(void* const* d_in, const int* in_sizes, int n_in,
                              void* d_out, int out_size)
{
    const float* x   = (const float*)d_in[0];   // [16,1024,16,12,30]
    const float* cls = (const float*)d_in[1];   // [16,16,1024]
    float* out = (float*)d_out;                 // [16,482,1024]

    k_scores<<<dim3(NB, CSPLIT), 96>>>(x, cls);
    k_mid<<<NB + 1536, 256>>>(x, cls, out);
    k_copy0<<<dim3(32, 3, NB), 256>>>(x, out);
}